// round 1
// baseline (speedup 1.0000x reference)
#include <cuda_runtime.h>
#include <cstdint>

#define T_TOK 16384
#define DIN   1280
#define DOUT  3840
#define RANK  16
#define NEXP  6
#define TOPK  3
#define KEXT  112               // 16 shared + 6*16 routed
#define KTOT  (DIN + KEXT)      // 1392

// Scratch (no cudaMalloc allowed)
__device__ __align__(16) float g_P[(size_t)T_TOK * KEXT];  // raw h: [shared(16) | routed(96)]
__device__ __align__(16) float g_G[(size_t)T_TOK * KEXT];  // gated + tf32-rounded A-extension

__device__ __forceinline__ float f2tf32f(float f) {
    uint32_t u;
    asm("cvt.rna.tf32.f32 %0, %1;" : "=r"(u) : "f"(f));
    return __uint_as_float(u);
}

__device__ __forceinline__ void mma_tf32(float c[4],
    uint32_t a0, uint32_t a1, uint32_t a2, uint32_t a3,
    uint32_t b0, uint32_t b1)
{
    asm volatile(
        "mma.sync.aligned.m16n8k8.row.col.f32.tf32.tf32.f32 "
        "{%0,%1,%2,%3}, {%4,%5,%6,%7}, {%8,%9}, {%0,%1,%2,%3};\n"
        : "+f"(c[0]), "+f"(c[1]), "+f"(c[2]), "+f"(c[3])
        : "r"(a0), "r"(a1), "r"(a2), "r"(a3), "r"(b0), "r"(b1));
}

// MODE 0: main GEMM  [T,1392] x [1392,3840]  A = [x | g_G], B = [base_w; shared_w2; routed_w2], +bias -> out
// MODE 1: prep GEMM  [T,1280] x [1280,112]   A = x,        B = [shared_w1 | routed_w1] (gather)  -> g_P
template<int MODE>
__global__ void __launch_bounds__(256) gemm_tf32_k(
    const float* __restrict__ x,
    const float* __restrict__ Bw0,   // MODE0: base_w     MODE1: shared_w1 [1280][16]
    const float* __restrict__ Bw1,   // MODE0: shared_w2  MODE1: routed_w1 [6][1280][16]
    const float* __restrict__ Bw2,   // MODE0: routed_w2  MODE1: unused
    const float* __restrict__ bias,  // MODE0: base_b     MODE1: unused
    float* __restrict__ out)         // MODE0: output     MODE1: unused (writes g_P)
{
    constexpr int NT = (MODE == 0) ? (KTOT / 16) : (DIN / 16);
    __shared__ __align__(16) float As[2][16][136];   // [k][m], pad 136 -> conflict-free frag loads
    __shared__ __align__(16) float Bs[2][16][136];   // [k][n]

    const int tid  = threadIdx.x;
    const int bm   = blockIdx.y * 128;
    const int bn   = blockIdx.x * 128;
    const int warp = tid >> 5;
    const int lane = tid & 31;
    const int wm   = (warp & 1) * 64;    // 2x4 warp grid, 64x32 per warp
    const int wn   = (warp >> 1) * 32;
    const int grp  = lane >> 2;
    const int tig  = lane & 3;

    // global->smem load mapping
    const int arow = tid >> 2;           // 0..63 (two rows: +0, +64)
    const int ak4  = (tid & 3) * 4;      // k offset 0,4,8,12
    const int bk   = tid >> 4;           // 0..15
    const int bn8  = (tid & 15) * 8;     // 0..120

    float acc[4][4][4];
    #pragma unroll
    for (int i = 0; i < 4; i++)
        #pragma unroll
        for (int j = 0; j < 4; j++)
            #pragma unroll
            for (int k = 0; k < 4; k++) acc[i][j][k] = 0.f;

    auto load_tile = [&](int kt, float4* ra, float4* rb) {
        const int k0 = kt * 16;
        #pragma unroll
        for (int i = 0; i < 2; i++) {
            const int m = bm + arow + i * 64;
            const int k = k0 + ak4;
            const float* p;
            if (MODE == 0 && k >= DIN) p = g_G + (size_t)m * KEXT + (k - DIN);
            else                       p = x   + (size_t)m * DIN  + k;
            ra[i] = *reinterpret_cast<const float4*>(p);
        }
        if (MODE == 0) {
            const int k = k0 + bk;
            const float* rowp;
            if (k < DIN)             rowp = Bw0 + (size_t)k * DOUT;
            else if (k < DIN + RANK) rowp = Bw1 + (size_t)(k - DIN) * DOUT;
            else                     rowp = Bw2 + (size_t)(k - DIN - RANK) * DOUT;
            rb[0] = *reinterpret_cast<const float4*>(rowp + bn + bn8);
            rb[1] = *reinterpret_cast<const float4*>(rowp + bn + bn8 + 4);
        } else {
            const int k = k0 + bk;
            float v[8];
            #pragma unroll
            for (int j = 0; j < 8; j++) {
                const int n = bn8 + j;
                float val = 0.f;
                if (n < RANK) {
                    val = Bw0[(size_t)k * RANK + n];
                } else if (n < KEXT) {
                    const int e = (n - RANK) >> 4;
                    const int r = (n - RANK) & 15;
                    val = Bw1[((size_t)e * DIN + k) * RANK + r];
                }
                v[j] = val;
            }
            rb[0] = make_float4(v[0], v[1], v[2], v[3]);
            rb[1] = make_float4(v[4], v[5], v[6], v[7]);
        }
    };

    auto store_tile = [&](int buf, const float4* ra, const float4* rb) {
        #pragma unroll
        for (int i = 0; i < 2; i++) {
            As[buf][ak4 + 0][arow + i * 64] = f2tf32f(ra[i].x);
            As[buf][ak4 + 1][arow + i * 64] = f2tf32f(ra[i].y);
            As[buf][ak4 + 2][arow + i * 64] = f2tf32f(ra[i].z);
            As[buf][ak4 + 3][arow + i * 64] = f2tf32f(ra[i].w);
        }
        float4 c0 = make_float4(f2tf32f(rb[0].x), f2tf32f(rb[0].y), f2tf32f(rb[0].z), f2tf32f(rb[0].w));
        float4 c1 = make_float4(f2tf32f(rb[1].x), f2tf32f(rb[1].y), f2tf32f(rb[1].z), f2tf32f(rb[1].w));
        *reinterpret_cast<float4*>(&Bs[buf][bk][bn8])     = c0;
        *reinterpret_cast<float4*>(&Bs[buf][bk][bn8 + 4]) = c1;
    };

    float4 ra[2], rb[2];
    load_tile(0, ra, rb);
    store_tile(0, ra, rb);
    __syncthreads();

    for (int kt = 0; kt < NT; kt++) {
        const int cur = kt & 1;
        const bool has_next = (kt + 1 < NT);
        float4 na[2], nb[2];
        if (has_next) load_tile(kt + 1, na, nb);

        #pragma unroll
        for (int ks = 0; ks < 2; ks++) {
            const int kb = ks * 8;
            uint32_t af[4][4], bf[4][2];
            #pragma unroll
            for (int mi = 0; mi < 4; mi++) {
                const int m0 = wm + mi * 16;
                af[mi][0] = __float_as_uint(As[cur][kb + tig    ][m0 + grp]);
                af[mi][1] = __float_as_uint(As[cur][kb + tig    ][m0 + grp + 8]);
                af[mi][2] = __float_as_uint(As[cur][kb + tig + 4][m0 + grp]);
                af[mi][3] = __float_as_uint(As[cur][kb + tig + 4][m0 + grp + 8]);
            }
            #pragma unroll
            for (int ni = 0; ni < 4; ni++) {
                const int n0 = wn + ni * 8;
                bf[ni][0] = __float_as_uint(Bs[cur][kb + tig    ][n0 + grp]);
                bf[ni][1] = __float_as_uint(Bs[cur][kb + tig + 4][n0 + grp]);
            }
            #pragma unroll
            for (int mi = 0; mi < 4; mi++)
                #pragma unroll
                for (int ni = 0; ni < 4; ni++)
                    mma_tf32(acc[mi][ni], af[mi][0], af[mi][1], af[mi][2], af[mi][3],
                             bf[ni][0], bf[ni][1]);
        }
        if (has_next) store_tile(cur ^ 1, na, nb);
        __syncthreads();
    }

    #pragma unroll
    for (int mi = 0; mi < 4; mi++) {
        #pragma unroll
        for (int ni = 0; ni < 4; ni++) {
            const int row = bm + wm + mi * 16 + grp;
            const int col = bn + wn + ni * 8 + tig * 2;
            if (MODE == 0) {
                const float b0 = bias[col], b1 = bias[col + 1];
                float2 v0 = make_float2(acc[mi][ni][0] + b0, acc[mi][ni][1] + b1);
                float2 v1 = make_float2(acc[mi][ni][2] + b0, acc[mi][ni][3] + b1);
                *reinterpret_cast<float2*>(out + (size_t)row * DOUT + col)       = v0;
                *reinterpret_cast<float2*>(out + (size_t)(row + 8) * DOUT + col) = v1;
            } else {
                if (col < KEXT) {
                    float2 v0 = make_float2(acc[mi][ni][0], acc[mi][ni][1]);
                    float2 v1 = make_float2(acc[mi][ni][2], acc[mi][ni][3]);
                    *reinterpret_cast<float2*>(g_P + (size_t)row * KEXT + col)       = v0;
                    *reinterpret_cast<float2*>(g_P + (size_t)(row + 8) * KEXT + col) = v1;
                }
            }
        }
    }
}

// One warp per token: exact fp32 router logits, softmax, top-3 gates, build gated
// tf32-rounded A-extension g_G from g_P.
__global__ void __launch_bounds__(256) router_combine_k(
    const float* __restrict__ x,
    const float* __restrict__ rtw,   // [1280][6]
    const float* __restrict__ rtb)   // [6]
{
    const int gwarp = (blockIdx.x * blockDim.x + threadIdx.x) >> 5;
    const int lane  = threadIdx.x & 31;
    if (gwarp >= T_TOK) return;

    const float* xr = x + (size_t)gwarp * DIN;
    float p[NEXP];
    #pragma unroll
    for (int e = 0; e < NEXP; e++) p[e] = 0.f;
    for (int k = lane; k < DIN; k += 32) {
        const float xv = xr[k];
        #pragma unroll
        for (int e = 0; e < NEXP; e++) p[e] += xv * rtw[k * NEXP + e];
    }
    #pragma unroll
    for (int e = 0; e < NEXP; e++) {
        #pragma unroll
        for (int o = 16; o > 0; o >>= 1) p[e] += __shfl_xor_sync(0xffffffffu, p[e], o);
        p[e] += rtb[e];
    }
    // softmax (all lanes redundantly)
    float mx = p[0];
    #pragma unroll
    for (int e = 1; e < NEXP; e++) mx = fmaxf(mx, p[e]);
    float ge[NEXP], s = 0.f;
    #pragma unroll
    for (int e = 0; e < NEXP; e++) { ge[e] = expf(p[e] - mx); s += ge[e]; }
    const float inv = 1.f / s;
    // top-3 -> combine weights
    float cw[NEXP], tmp[NEXP];
    #pragma unroll
    for (int e = 0; e < NEXP; e++) { cw[e] = 0.f; tmp[e] = ge[e]; }
    #pragma unroll
    for (int it = 0; it < TOPK; it++) {
        int bi = 0; float bv = tmp[0];
        #pragma unroll
        for (int e = 1; e < NEXP; e++) if (tmp[e] > bv) { bv = tmp[e]; bi = e; }
        cw[bi] = ge[bi] * inv;
        tmp[bi] = -1.f;
    }
    // gate + tf32-round the extension vector
    for (int j = lane; j < KEXT; j += 32) {
        float v = g_P[(size_t)gwarp * KEXT + j];
        if (j >= RANK) v *= cw[(j - RANK) >> 4];
        g_G[(size_t)gwarp * KEXT + j] = f2tf32f(v);
    }
}

extern "C" void kernel_launch(void* const* d_in, const int* in_sizes, int n_in,
                              void* d_out, int out_size)
{
    const float* x    = (const float*)d_in[0];
    const float* bw   = (const float*)d_in[1];
    const float* bb   = (const float*)d_in[2];
    const float* sw1  = (const float*)d_in[3];
    const float* sw2  = (const float*)d_in[4];
    const float* rw1  = (const float*)d_in[5];
    const float* rw2  = (const float*)d_in[6];
    const float* rtw  = (const float*)d_in[7];
    const float* rtb  = (const float*)d_in[8];
    float* out = (float*)d_out;

    // 1) h vectors (tf32 mma): g_P[t][0:16]=shared h, [16:112]=routed h
    gemm_tf32_k<1><<<dim3(1, T_TOK / 128), 256>>>(x, sw1, rw1, nullptr, nullptr, nullptr);
    // 2) exact-fp32 router + top-3 gating -> g_G (tf32-rounded)
    router_combine_k<<<T_TOK / 8, 256>>>(x, rtw, rtb);
    // 3) fused main GEMM: out = [x|g_G] @ [base_w; shared_w2; routed_w2] + base_b
    gemm_tf32_k<0><<<dim3(DOUT / 128, T_TOK / 128), 256>>>(x, bw, sw2, rw2, bb, out);
}